// round 16
// baseline (speedup 1.0000x reference)
#include <cuda_runtime.h>
#include <cuda_bf16.h>
#include <math.h>
#include <stdint.h>

// HFALoss: N=4096, C=1000 (pad 1024), A=64.
// d^T CV d = q_cc - w_c.u_n + r_n ; q via sym-packed GEMM (K1=2080) + cross tail (64).
// Q[4096x1024] = Apack @ Gpack^T in bf16 mma.sync m16n8k16 (ldmatrix, double-buffered
// fragments, 64x64 warp tiles, BK=128 stages x2); softmax + Y + combine + loss fused.
#define NB    4096
#define CC    1000
#define CPAD  1024
#define AA    64
#define KTRI  2080
#define KP    2144            // real K
#define KP2   2176            // padded: 17*128
#define KT128 17              // 128-wide k tiles
#define KB32  68              // 32-wide k blocks incl. pad
#define BM    128
#define BN    256
#define NCTA_C (CPAD / BN)    // 4

#define A_TILE_B 32768        // [phase(8)][row(128)][32B], chunk swizzled by (row>>2)&1
#define B_TILE_B 65536        // [h(4)][col(256)][64B], chunk swizzled by (col>>1)&3
#define STAGE_B  (A_TILE_B + B_TILE_B)    // 98304
#define STAGES   2
#define SMEM_TOTAL (STAGES * STAGE_B)     // 196608

// ---------------- device scratch ----------------
__device__ __align__(128) __nv_bfloat16 g_A[(size_t)NB * KP2];          // 17.8 MB
__device__ __align__(128) __nv_bfloat16 g_B[(size_t)KB32 * CPAD * 32];  //  4.5 MB
__device__ float  g_rowconst[NB];
__device__ float  g_w2[CPAD];
__device__ float  g_pmax[NCTA_C * NB];
__device__ float  g_psum[NCTA_C * NB];
__device__ float  g_lk[NB];
__device__ float  g_nll[NB];
__device__ int    g_cnt_row[NB / BM];
__device__ int    g_cnt_all;
__device__ float  g_dummy;

__device__ __forceinline__ void cpasync16(uint32_t s, const void* g) {
    asm volatile("cp.async.cg.shared.global [%0], [%1], 16;\n" :: "r"(s), "l"(g));
}
__device__ __forceinline__ uint32_t smem_u32(const void* p) {
    uint32_t a;
    asm("{ .reg .u64 t; cvta.to.shared.u64 t, %1; cvt.u32.u64 %0, t; }" : "=r"(a) : "l"(p));
    return a;
}
__device__ __forceinline__ void ldsm4(uint32_t* r, uint32_t addr) {
    asm volatile("ldmatrix.sync.aligned.m8n8.x4.shared.b16 {%0,%1,%2,%3}, [%4];"
                 : "=r"(r[0]), "=r"(r[1]), "=r"(r[2]), "=r"(r[3]) : "r"(addr));
}
__device__ __forceinline__ void mma_bf16(float* c, const uint32_t* a, const uint32_t* b) {
    asm volatile(
        "mma.sync.aligned.m16n8k16.row.col.f32.bf16.bf16.f32 "
        "{%0,%1,%2,%3}, {%4,%5,%6,%7}, {%8,%9}, {%0,%1,%2,%3};"
        : "+f"(c[0]), "+f"(c[1]), "+f"(c[2]), "+f"(c[3])
        : "r"(a[0]), "r"(a[1]), "r"(a[2]), "r"(a[3]), "r"(b[0]), "r"(b[1]));
}
// exp(x) for x in [-87, 0] without MUFU.
__device__ __forceinline__ float fexp_fma(float x) {
    float t = x * 1.4426950408889634f;
    float fn = rintf(t);
    float f = t - fn;
    float p = 1.5403530393381608e-4f;
    p = fmaf(p, f, 1.3333558146428443e-3f);
    p = fmaf(p, f, 9.6181291076284772e-3f);
    p = fmaf(p, f, 5.5504108664821580e-2f);
    p = fmaf(p, f, 2.4022650695910072e-1f);
    p = fmaf(p, f, 6.9314718055994531e-1f);
    p = fmaf(p, f, 1.0f);
    return __int_as_float(__float_as_int(p) + (((int)fn) << 23));
}
// analytic packed idx -> (a,b), a<=b ; base(a) = a*(129-a)/2
__device__ __forceinline__ int2 l2ab(int l) {
    float disc = 16641.0f - 8.0f * (float)l;
    int a = (int)((129.0f - sqrtf(disc)) * 0.5f);
    while (a > 0 && a * (129 - a) / 2 > l) a--;
    while ((a + 1) * (129 - (a + 1)) / 2 <= l) a++;
    int b = a + (l - a * (129 - a) / 2);
    return make_int2(a, b);
}

// ---------------- merged prep: blocks [0,64) build G, [64,64+NB) build A ----------------
__global__ void __launch_bounds__(256) prep_kernel(
    const float* __restrict__ W, const int* __restrict__ tgt,
    const float* __restrict__ ratio_p, const float* __restrict__ CV)
{
    const int tid = threadIdx.x;
    if (blockIdx.x < 64) {
        // ---- G mode: 16 classes ----
        __shared__ float sw[16][65];
        const int c0 = blockIdx.x * 16;
        if (blockIdx.x == 0 && tid < NB / BM + 1) {
            if (tid < NB / BM) g_cnt_row[tid] = 0;
            else g_cnt_all = 0;
        }
        for (int idx = tid; idx < 16 * 64; idx += 256) {
            int ci = idx >> 6, a = idx & 63;
            sw[ci][a] = (c0 + ci < CC) ? W[(c0 + ci) * AA + a] : 0.f;
        }
        __syncthreads();
        if (tid < 16) {
            float s = 0.f;
            #pragma unroll
            for (int a = 0; a < AA; a++) s = fmaf(sw[tid][a], sw[tid][a], s);
            g_w2[c0 + tid] = s;
        }
        uint32_t* gB32 = reinterpret_cast<uint32_t*>(g_B);
        for (int ci = 0; ci < 16; ci++) {
            const int c = c0 + ci;
            for (int l2 = tid; l2 < KP2 / 2; l2 += 256) {
                int l = 2 * l2;
                float v0 = 0.f, v1 = 0.f;
                if (l < KTRI) {
                    int2 ab0 = l2ab(l), ab1 = l2ab(l + 1);
                    v0 = sw[ci][ab0.x] * sw[ci][ab0.y];
                    v1 = sw[ci][ab1.x] * sw[ci][ab1.y];
                } else if (l < KP) {
                    v0 = sw[ci][l - KTRI];
                    v1 = sw[ci][l + 1 - KTRI];
                }
                __nv_bfloat162 h = __floats2bfloat162_rn(v0, v1);
                int kt = l >> 5, k = l & 31;
                gB32[((size_t)kt * CPAD + c) * 16 + (k >> 1)] = *reinterpret_cast<uint32_t*>(&h);
            }
        }
    } else {
        // ---- A mode: one sample ----
        __shared__ float sM[AA * 65];
        __shared__ float swk[AA];
        __shared__ float su[AA];
        __shared__ float pr[4][AA], pc[4][AA];
        __shared__ float red[AA], red2[AA];
        const int n = blockIdx.x - 64;
        const int k = tgt[n];

        const float4* cv4 = reinterpret_cast<const float4*>(CV + (size_t)n * AA * AA);
        #pragma unroll
        for (int i = 0; i < 4; i++) {
            int idx4 = tid + i * 256;
            float4 v = cv4[idx4];
            int row = idx4 >> 4, cc0 = (idx4 & 15) * 4;
            float* d = sM + row * 65 + cc0;
            d[0] = v.x; d[1] = v.y; d[2] = v.z; d[3] = v.w;
        }
        if (tid < AA) swk[tid] = W[k * AA + tid];
        __syncthreads();

        {
            int a = tid & 63, part = tid >> 6;
            float tr = 0.f, tc = 0.f;
            int b0 = part * 16;
            #pragma unroll
            for (int j = 0; j < 16; j++) {
                int b = b0 + j;
                float wb = swk[b];
                tr = fmaf(sM[a * 65 + b], wb, tr);
                tc = fmaf(sM[b * 65 + a], wb, tc);
            }
            pr[part][a] = tr; pc[part][a] = tc;
        }
        __syncthreads();
        if (tid < AA) {
            float trow = pr[0][tid] + pr[1][tid] + pr[2][tid] + pr[3][tid];
            float tcol = pc[0][tid] + pc[1][tid] + pc[2][tid] + pc[3][tid];
            su[tid]   = trow + tcol;
            red[tid]  = swk[tid] * trow;
            red2[tid] = swk[tid] * swk[tid];
        }
        __syncthreads();
        if (tid < 32) {
            float r  = red[tid] + red[tid + 32];
            float r2 = red2[tid] + red2[tid + 32];
            #pragma unroll
            for (int off = 16; off > 0; off >>= 1) {
                r  += __shfl_xor_sync(0xffffffffu, r, off);
                r2 += __shfl_xor_sync(0xffffffffu, r2, off);
            }
            if (tid == 0) g_rowconst[n] = fmaf(0.5f * ratio_p[0], r, -r2);
        }

        uint32_t* row32 = reinterpret_cast<uint32_t*>(g_A + (size_t)n * KP2);
        for (int l2 = tid; l2 < KP2 / 2; l2 += 256) {
            int l = 2 * l2;
            float v0 = 0.f, v1 = 0.f;
            if (l < KTRI) {
                int2 ab0 = l2ab(l), ab1 = l2ab(l + 1);
                v0 = (ab0.x == ab0.y) ? sM[ab0.x * 65 + ab0.x]
                                      : sM[ab0.x * 65 + ab0.y] + sM[ab0.y * 65 + ab0.x];
                v1 = (ab1.x == ab1.y) ? sM[ab1.x * 65 + ab1.x]
                                      : sM[ab1.x * 65 + ab1.y] + sM[ab1.y * 65 + ab1.x];
            } else if (l < KP) {
                v0 = -su[l - KTRI];
                v1 = -su[l + 1 - KTRI];
            }
            __nv_bfloat162 h = __floats2bfloat162_rn(v0, v1);
            row32[l2] = *reinterpret_cast<uint32_t*>(&h);
        }
    }
}

// ---------------- GEMM (256 thr, 8 warps x 64x64, BK=128, 2 stages) + fusions ----------------
__global__ void __launch_bounds__(256, 1) gemm_kernel(
    const float* __restrict__ ratio_p, const float* __restrict__ Y,
    const int* __restrict__ tgt, float* __restrict__ yout,
    float* __restrict__ lossout)
{
    extern __shared__ char smem[];
    const uint32_t sbase = smem_u32(smem);
    const int tid  = threadIdx.x;
    const int wid  = tid >> 5;
    const int lane = tid & 31;
    const int gid  = lane >> 2;
    const int tig  = lane & 3;
    const int m0 = blockIdx.x * BM;
    const int c0 = blockIdx.y * BN;
    const int wm0 = (wid >> 2) * 64;     // 0, 64
    const int wn0 = (wid & 3) * 64;      // 0,64,128,192

    // ldmatrix lane-constant offsets
    const int l15 = lane & 15;
    const uint32_t A_lane_off = (uint32_t)(l15 * 32 + (((lane >> 4) ^ ((l15 >> 2) & 1)) << 4));
    const int swz3 = (l15 >> 1) & 3;
    const uint32_t B_col_base = (uint32_t)((wn0 + l15) * 64);
    const int bq_half = lane >> 4;

    // fill bases: A chunk ch = tid + i*256 -> r = (tid>>4)+16i (j = tid&15 fixed)
    //   smem stride/i = 16 rows * 32B = 512 (swizzle parity invariant under r+=16)
    //   gmem stride/i = 16 * KP2*2 = 69632
    // B chunk ch = tid + i*256 -> h = i>>2, c = (tid>>2)+64*(i&3), cq = tid&3
    //   smem: h*16384 + c*64 + swz  -> base + i*4096 (swizzle invariant under c+=64)
    //   gmem: h*CPAD*64 + c*64 + cq*16 -> base + (i>>2)*65536 + (i&3)*4096
    uint32_t aS0, aG0, bS0, bG0;
    {
        int r = tid >> 4, j = tid & 15;
        aS0 = (uint32_t)((j >> 1) * 4096 + r * 32 + (((j & 1) ^ ((r >> 2) & 1)) << 4));
        aG0 = (uint32_t)((m0 + r) * (KP2 * 2) + j * 16);
        int c = tid >> 2, cq = tid & 3;
        bS0 = (uint32_t)(c * 64 + ((cq ^ ((c >> 1) & 3)) << 4));
        bG0 = (uint32_t)(c * 64 + cq * 16);
    }
    const char* pA = reinterpret_cast<const char*>(g_A);                     // +256B/fill
    const char* pB = reinterpret_cast<const char*>(g_B) + (size_t)c0 * 64;   // +CPAD*256/fill

    float acc[4][8][4];
    #pragma unroll
    for (int i = 0; i < 4; i++)
        #pragma unroll
        for (int j = 0; j < 8; j++)
            #pragma unroll
            for (int r = 0; r < 4; r++) acc[i][j][r] = 0.f;

    auto fill = [&](int s) {
        uint32_t bA = sbase + s * STAGE_B + aS0;
        uint32_t bB = sbase + s * STAGE_B + A_TILE_B + bS0;
        #pragma unroll
        for (int i = 0; i < 8; i++)
            cpasync16(bA + i * 512, pA + aG0 + i * 69632);
        #pragma unroll
        for (int i = 0; i < 16; i++)
            cpasync16(bB + i * 4096, pB + bG0 + (i >> 2) * 65536 + (i & 3) * 4096);
        asm volatile("cp.async.commit_group;\n" ::: "memory");
        pA += 256;
        pB += (size_t)CPAD * 256;
    };

    uint32_t f0a[4][4], f0b[8][2], f1a[4][4], f1b[8][2];

    // phase p in 0..7: A offset p*4096; B offset (p>>1)*16384, q=(p&1)*2+bq_half
    auto ldA = [&](uint32_t bA, int p, uint32_t a[4][4]) {
        #pragma unroll
        for (int mt = 0; mt < 4; mt++)
            ldsm4(a[mt], bA + p * 4096 + (wm0 + mt * 16) * 32 + A_lane_off);
    };
    auto ldB = [&](uint32_t bB, int p, uint32_t b[8][2]) {
        #pragma unroll
        for (int ntp = 0; ntp < 4; ntp++) {
            uint32_t r[4];
            int q = (p & 1) * 2 + bq_half;
            ldsm4(r, bB + (p >> 1) * 16384 + B_col_base + ntp * 1024 + ((q ^ swz3) << 4));
            b[2 * ntp][0] = r[0]; b[2 * ntp][1] = r[2];
            b[2 * ntp + 1][0] = r[1]; b[2 * ntp + 1][1] = r[3];
        }
    };
    auto mma_all = [&](uint32_t a[4][4], uint32_t b[8][2]) {
        #pragma unroll
        for (int mt = 0; mt < 4; mt++)
            #pragma unroll
            for (int nt = 0; nt < 8; nt++)
                mma_bf16(acc[mt][nt], a[mt], b[nt]);
    };

    fill(0); fill(1);
    asm volatile("cp.async.wait_group 1;\n" ::: "memory");
    __syncthreads();
    ldA(sbase, 0, f0a); ldB(sbase + A_TILE_B, 0, f0b);

    int s = 0;
    for (int kt = 0; kt < KT128; kt++) {
        const uint32_t bA = sbase + s * STAGE_B;
        const uint32_t bB = bA + A_TILE_B;
        ldA(bA, 1, f1a); ldB(bB, 1, f1b);
        mma_all(f0a, f0b);
        ldA(bA, 2, f0a); ldB(bB, 2, f0b);
        mma_all(f1a, f1b);
        ldA(bA, 3, f1a); ldB(bB, 3, f1b);
        mma_all(f0a, f0b);
        ldA(bA, 4, f0a); ldB(bB, 4, f0b);
        mma_all(f1a, f1b);
        ldA(bA, 5, f1a); ldB(bB, 5, f1b);
        mma_all(f0a, f0b);
        ldA(bA, 6, f0a); ldB(bB, 6, f0b);
        mma_all(f1a, f1b);
        ldA(bA, 7, f1a); ldB(bB, 7, f1b);
        mma_all(f0a, f0b);
        // all reads of stage s done; next tile (stage s^1) must be resident
        asm volatile("cp.async.wait_group 0;\n" ::: "memory");
        __syncthreads();
        if (kt + 2 < KT128) fill(s);        // refill freed stage with tile kt+2
        int s1 = s ^ 1;
        if (kt + 1 < KT128) {
            uint32_t bA1 = sbase + s1 * STAGE_B;
            ldA(bA1, 0, f0a); ldB(bA1 + A_TILE_B, 0, f0b);
        }
        mma_all(f1a, f1b);
        s = s1;
    }
    __syncthreads();   // mainloop smem dead; reuse for reductions

    // ---- fused epilogue: per-row (max, sumexp) partial + target logit + Y out ----
    float* sR = reinterpret_cast<float*>(smem);         // [8][64]
    float* sS = reinterpret_cast<float*>(smem) + 512;   // [8][64]
    int*   sFlag = reinterpret_cast<int*>(smem) + 1024;
    const float hr = 0.5f * ratio_p[0];

    int   tcol[4][2];
    float rc[4][2];
    #pragma unroll
    for (int mt = 0; mt < 4; mt++)
        #pragma unroll
        for (int h = 0; h < 2; h++) {
            int rglob = m0 + wm0 + mt * 16 + gid + 8 * h;
            tcol[mt][h] = tgt[rglob];
            rc[mt][h] = g_rowconst[rglob];
        }

    float rmax[4][2];
    #pragma unroll
    for (int mt = 0; mt < 4; mt++) { rmax[mt][0] = -1e30f; rmax[mt][1] = -1e30f; }

    #pragma unroll
    for (int nt = 0; nt < 8; nt++) {
        int col = c0 + wn0 + nt * 8 + 2 * tig;
        bool ok = (col < CC);          // col even, CC even -> col+1 < CC too
        float w20 = g_w2[col], w21 = g_w2[col + 1];
        #pragma unroll
        for (int mt = 0; mt < 4; mt++) {
            #pragma unroll
            for (int h = 0; h < 2; h++) {
                int rglob = m0 + wm0 + mt * 16 + gid + 8 * h;
                float y0 = 0.f, y1 = 0.f;
                if (ok) {
                    float2 yv = *reinterpret_cast<const float2*>(Y + (size_t)rglob * CC + col);
                    y0 = yv.x; y1 = yv.y;
                    if (yout) {
                        // scalar stores: yout = out+1 is only 4B-aligned
                        yout[(size_t)rglob * CC + col]     = y0;
                        yout[(size_t)rglob * CC + col + 1] = y1;
                    }
                }
                float v0 = ok ? fmaf(hr, acc[mt][nt][2 * h + 0], rc[mt][h] + w20 + y0) : -1e30f;
                float v1 = ok ? fmaf(hr, acc[mt][nt][2 * h + 1], rc[mt][h] + w21 + y1) : -1e30f;
                if (col == tcol[mt][h])     g_lk[rglob] = v0;
                if (col + 1 == tcol[mt][h]) g_lk[rglob] = v1;
                acc[mt][nt][2 * h + 0] = v0;
                acc[mt][nt][2 * h + 1] = v1;
                rmax[mt][h] = fmaxf(rmax[mt][h], fmaxf(v0, v1));
            }
        }
    }
    #pragma unroll
    for (int mt = 0; mt < 4; mt++)
        #pragma unroll
        for (int h = 0; h < 2; h++) {
            rmax[mt][h] = fmaxf(rmax[mt][h], __shfl_xor_sync(0xffffffffu, rmax[mt][h], 1));
            rmax[mt][h] = fmaxf(rmax[mt][h], __shfl_xor_sync(0xffffffffu, rmax[mt][h], 2));
        }
    if (tig == 0) {
        #pragma unroll
        for (int mt = 0; mt < 4; mt++)
            #pragma unroll
            for (int h = 0; h < 2; h++)
                sR[wid * 64 + mt * 16 + gid + 8 * h] = rmax[mt][h];
    }
    __syncthreads();
    const int wg4 = (wid >> 2) * 4;
    float Mf[4][2];
    #pragma unroll
    for (int mt = 0; mt < 4; mt++)
        #pragma unroll
        for (int h = 0; h < 2; h++) {
            int idx = mt * 16 + gid + 8 * h;
            float mv = sR[wg4 * 64 + idx];
            mv = fmaxf(mv, sR[(wg4 + 1) * 64 + idx]);
            mv = fmaxf(mv, sR[(wg4 + 2) * 64 + idx]);
            mv = fmaxf(mv, sR[(wg4 + 3) * 64 + idx]);
            Mf[mt][h] = mv;
        }
    float rsum[4][2];
    #pragma unroll
    for (int mt = 0; mt < 4; mt++) { rsum[mt][0] = 0.f; rsum[mt][1] = 0.f; }
    #pragma unroll
    for (int nt = 0; nt < 8; nt++)
        #pragma unroll
        for (int mt = 0; mt < 4; mt++)
            #pragma unroll
            for (int h = 0; h < 2; h++) {
                rsum[mt][h] += fexp_fma(fmaxf(acc[mt][nt][2 * h + 0] - Mf[mt][h], -80.f));
                rsum[mt][h] += fexp_fma(fmaxf(acc[mt][nt][2 * h + 1] - Mf[mt][h], -80.f));
            }
    #pragma unroll
    for (int mt = 0; mt < 4; mt++)
        #pragma unroll
        for (int h = 0; h < 2; h++) {
            rsum[mt][h] += __shfl_xor_sync(0xffffffffu, rsum[mt][h], 1);
            rsum[mt][h] += __shfl_xor_sync(0xffffffffu, rsum[mt][h], 2);
        }
    __syncthreads();
    if (tig == 0) {
        #pragma unroll
        for (int mt = 0; mt < 4; mt++)
            #pragma unroll
            for (int h = 0; h < 2; h++)
                sS[wid * 64 + mt * 16 + gid + 8 * h] = rsum[mt][h];
    }
    __syncthreads();
    if (tig == 0 && (wid & 3) == 0) {
        const int ct = blockIdx.y;
        #pragma unroll
        for (int mt = 0; mt < 4; mt++)
            #pragma unroll
            for (int h = 0; h < 2; h++) {
                int idx = mt * 16 + gid + 8 * h;
                int rglob = m0 + wm0 + idx;
                float ssum = sS[wg4 * 64 + idx] + sS[(wg4 + 1) * 64 + idx]
                           + sS[(wg4 + 2) * 64 + idx] + sS[(wg4 + 3) * 64 + idx];
                g_pmax[ct * NB + rglob] = Mf[mt][h];
                g_psum[ct * NB + rglob] = ssum;
            }
    }

    // ---- fused cross-CTA combine ----
    __threadfence();
    __syncthreads();
    if (tid == 0) sFlag[0] = atomicAdd(&g_cnt_row[blockIdx.x], 1);
    __syncthreads();
    if (sFlag[0] != NCTA_C - 1) return;

    __threadfence();
    if (tid < BM) {
        int n = m0 + tid;
        float M = g_pmax[n];
        #pragma unroll
        for (int i = 1; i < NCTA_C; i++) M = fmaxf(M, g_pmax[i * NB + n]);
        float S = 0.f;
        #pragma unroll
        for (int i = 0; i < NCTA_C; i++)
            S += g_psum[i * NB + n] * fexp_fma(fmaxf(g_pmax[i * NB + n] - M, -80.f));
        g_nll[n] = (M + logf(S)) - g_lk[n];
    }
    __threadfence();
    __syncthreads();
    if (tid == 0) sFlag[0] = atomicAdd(&g_cnt_all, 1);
    __syncthreads();
    if (sFlag[0] != NB / BM - 1) return;

    __threadfence();
    float accl = 0.f;
    const float4* p = reinterpret_cast<const float4*>(g_nll);
    for (int i = tid; i < NB / 4; i += 256) {
        float4 v = p[i];
        accl += (v.x + v.y) + (v.z + v.w);
    }
    sR[tid] = accl;
    __syncthreads();
    #pragma unroll
    for (int off = 128; off > 0; off >>= 1) {
        if (tid < off) sR[tid] += sR[tid + off];
        __syncthreads();
    }
    if (tid == 0) lossout[0] = sR[0] * (1.0f / NB);
}

// ---------------- host ----------------
extern "C" void kernel_launch(void* const* d_in, const int* in_sizes, int n_in,
                              void* d_out, int out_size)
{
    const float* W     = (const float*)d_in[0];
    const float* Y     = (const float*)d_in[1];
    const int*   tgt   = (const int*)  d_in[3];
    const float* ratio = (const float*)d_in[4];
    const float* CV    = (const float*)d_in[5];
    float* out = (float*)d_out;

    cudaFuncSetAttribute(gemm_kernel, cudaFuncAttributeMaxDynamicSharedMemorySize, SMEM_TOTAL);

    const bool std_layout = (out_size >= 1 + NB * CC);
    float* yout = std_layout ? (out + 1) : nullptr;
    float* lossout;
    if (std_layout) lossout = out;
    else cudaGetSymbolAddress((void**)&lossout, g_dummy);

    prep_kernel<<<64 + NB, 256>>>(W, tgt, ratio, CV);
    gemm_kernel<<<dim3(NB / BM, CPAD / BN), 256, SMEM_TOTAL>>>(ratio, Y, tgt, yout, lossout);

    if (!std_layout && out_size == NB * CC) {
        cudaMemcpyAsync(out, Y, (size_t)NB * CC * sizeof(float),
                        cudaMemcpyDeviceToDevice, 0);
    }
}

// round 17
// speedup vs baseline: 1.0616x; 1.0616x over previous
#include <cuda_runtime.h>
#include <cuda_bf16.h>
#include <math.h>
#include <stdint.h>

// HFALoss: N=4096, C=1000 (pad 1024), A=64.
// d^T CV d = q_cc - w_c.u_n + r_n ; q via sym-packed GEMM (K1=2080) + cross tail (64).
// Q[4096x1024] = Apack @ Gpack^T in bf16 mma.sync m16n8k16 (ldmatrix, double-buffered
// fragments, 64x64 warp tiles, BK=64 x 4 stages); softmax + Y + combine + loss fused.
#define NB    4096
#define CC    1000
#define CPAD  1024
#define AA    64
#define KTRI  2080
#define KP    2144            // real K
#define KP2   2176            // padded to 34*64 (zeros in pad)
#define KT2   34              // 64-wide k tiles
#define KB32  68              // 32-wide k blocks incl. pad
#define BM    128
#define BN    256
#define NCTA_C (CPAD / BN)    // 4

#define A_TILE_B 16384        // [half(2)][ks(2)][row(128)][32B], swizzle (row>>2)&1
#define B_TILE_B 32768        // [half(2)][col(256)][64B], swizzle (col>>1)&3
#define STAGE_B  (A_TILE_B + B_TILE_B)    // 49152
#define STAGES   4
#define SMEM_TOTAL (STAGES * STAGE_B)     // 196608

// ---------------- device scratch ----------------
__device__ __align__(128) __nv_bfloat16 g_A[(size_t)NB * KP2];          // 17.8 MB
__device__ __align__(128) __nv_bfloat16 g_B[(size_t)KB32 * CPAD * 32];  //  4.5 MB
__device__ float  g_rowconst[NB];
__device__ float  g_w2[CPAD];
__device__ float  g_pmax[NCTA_C * NB];
__device__ float  g_psum[NCTA_C * NB];
__device__ float  g_lk[NB];
__device__ float  g_nll[NB];
__device__ int    g_cnt_row[NB / BM];
__device__ int    g_cnt_all;
__device__ float  g_dummy;

__device__ __forceinline__ void cpasync16(uint32_t s, const void* g) {
    asm volatile("cp.async.cg.shared.global [%0], [%1], 16;\n" :: "r"(s), "l"(g));
}
__device__ __forceinline__ uint32_t smem_u32(const void* p) {
    uint32_t a;
    asm("{ .reg .u64 t; cvta.to.shared.u64 t, %1; cvt.u32.u64 %0, t; }" : "=r"(a) : "l"(p));
    return a;
}
__device__ __forceinline__ void ldsm4(uint32_t* r, uint32_t addr) {
    asm volatile("ldmatrix.sync.aligned.m8n8.x4.shared.b16 {%0,%1,%2,%3}, [%4];"
                 : "=r"(r[0]), "=r"(r[1]), "=r"(r[2]), "=r"(r[3]) : "r"(addr));
}
__device__ __forceinline__ void mma_bf16(float* c, const uint32_t* a, const uint32_t* b) {
    asm volatile(
        "mma.sync.aligned.m16n8k16.row.col.f32.bf16.bf16.f32 "
        "{%0,%1,%2,%3}, {%4,%5,%6,%7}, {%8,%9}, {%0,%1,%2,%3};"
        : "+f"(c[0]), "+f"(c[1]), "+f"(c[2]), "+f"(c[3])
        : "r"(a[0]), "r"(a[1]), "r"(a[2]), "r"(a[3]), "r"(b[0]), "r"(b[1]));
}
// exp(x) for x in [-87, 0] without MUFU.
__device__ __forceinline__ float fexp_fma(float x) {
    float t = x * 1.4426950408889634f;
    float fn = rintf(t);
    float f = t - fn;
    float p = 1.5403530393381608e-4f;
    p = fmaf(p, f, 1.3333558146428443e-3f);
    p = fmaf(p, f, 9.6181291076284772e-3f);
    p = fmaf(p, f, 5.5504108664821580e-2f);
    p = fmaf(p, f, 2.4022650695910072e-1f);
    p = fmaf(p, f, 6.9314718055994531e-1f);
    p = fmaf(p, f, 1.0f);
    return __int_as_float(__float_as_int(p) + (((int)fn) << 23));
}
// analytic packed idx -> (a,b), a<=b ; base(a) = a*(129-a)/2
__device__ __forceinline__ int2 l2ab(int l) {
    float disc = 16641.0f - 8.0f * (float)l;
    int a = (int)((129.0f - sqrtf(disc)) * 0.5f);
    while (a > 0 && a * (129 - a) / 2 > l) a--;
    while ((a + 1) * (129 - (a + 1)) / 2 <= l) a++;
    int b = a + (l - a * (129 - a) / 2);
    return make_int2(a, b);
}

// ---------------- merged prep: blocks [0,64) build G, [64,64+NB/2) build A (2 samples) ----------------
__global__ void __launch_bounds__(256) prep_kernel(
    const float* __restrict__ W, const int* __restrict__ tgt,
    const float* __restrict__ ratio_p, const float* __restrict__ CV)
{
    const int tid = threadIdx.x;
    if (blockIdx.x < 64) {
        // ---- G mode: 16 classes ----
        __shared__ float sw[16][65];
        const int c0 = blockIdx.x * 16;
        if (blockIdx.x == 0 && tid < NB / BM + 1) {
            if (tid < NB / BM) g_cnt_row[tid] = 0;
            else g_cnt_all = 0;
        }
        for (int idx = tid; idx < 16 * 64; idx += 256) {
            int ci = idx >> 6, a = idx & 63;
            sw[ci][a] = (c0 + ci < CC) ? W[(c0 + ci) * AA + a] : 0.f;
        }
        __syncthreads();
        if (tid < 16) {
            float s = 0.f;
            #pragma unroll
            for (int a = 0; a < AA; a++) s = fmaf(sw[tid][a], sw[tid][a], s);
            g_w2[c0 + tid] = s;
        }
        uint32_t* gB32 = reinterpret_cast<uint32_t*>(g_B);
        for (int ci = 0; ci < 16; ci++) {
            const int c = c0 + ci;
            for (int l2 = tid; l2 < KP2 / 2; l2 += 256) {
                int l = 2 * l2;
                float v0 = 0.f, v1 = 0.f;
                if (l < KTRI) {
                    int2 ab0 = l2ab(l), ab1 = l2ab(l + 1);
                    v0 = sw[ci][ab0.x] * sw[ci][ab0.y];
                    v1 = sw[ci][ab1.x] * sw[ci][ab1.y];
                } else if (l < KP) {
                    v0 = sw[ci][l - KTRI];
                    v1 = sw[ci][l + 1 - KTRI];
                }
                __nv_bfloat162 h = __floats2bfloat162_rn(v0, v1);
                int kt = l >> 5, k = l & 31;
                gB32[((size_t)kt * CPAD + c) * 16 + (k >> 1)] = *reinterpret_cast<uint32_t*>(&h);
            }
        }
    } else {
        // ---- A mode: two samples, sequential, smem reused ----
        __shared__ float sM[AA * 65];
        __shared__ float swk[AA];
        __shared__ float su[AA];
        __shared__ float pr[4][AA], pc[4][AA];
        __shared__ float red[AA], red2[AA];
        #pragma unroll 1
        for (int rep = 0; rep < 2; rep++) {
            const int n = 2 * (blockIdx.x - 64) + rep;
            const int k = tgt[n];

            const float4* cv4 = reinterpret_cast<const float4*>(CV + (size_t)n * AA * AA);
            #pragma unroll
            for (int i = 0; i < 4; i++) {
                int idx4 = tid + i * 256;
                float4 v = cv4[idx4];
                int row = idx4 >> 4, cc0 = (idx4 & 15) * 4;
                float* d = sM + row * 65 + cc0;
                d[0] = v.x; d[1] = v.y; d[2] = v.z; d[3] = v.w;
            }
            if (tid < AA) swk[tid] = W[k * AA + tid];
            __syncthreads();

            {
                int a = tid & 63, part = tid >> 6;
                float tr = 0.f, tc = 0.f;
                int b0 = part * 16;
                #pragma unroll
                for (int j = 0; j < 16; j++) {
                    int b = b0 + j;
                    float wb = swk[b];
                    tr = fmaf(sM[a * 65 + b], wb, tr);
                    tc = fmaf(sM[b * 65 + a], wb, tc);
                }
                pr[part][a] = tr; pc[part][a] = tc;
            }
            __syncthreads();
            if (tid < AA) {
                float trow = pr[0][tid] + pr[1][tid] + pr[2][tid] + pr[3][tid];
                float tcol = pc[0][tid] + pc[1][tid] + pc[2][tid] + pc[3][tid];
                su[tid]   = trow + tcol;
                red[tid]  = swk[tid] * trow;
                red2[tid] = swk[tid] * swk[tid];
            }
            __syncthreads();
            if (tid < 32) {
                float r  = red[tid] + red[tid + 32];
                float r2 = red2[tid] + red2[tid + 32];
                #pragma unroll
                for (int off = 16; off > 0; off >>= 1) {
                    r  += __shfl_xor_sync(0xffffffffu, r, off);
                    r2 += __shfl_xor_sync(0xffffffffu, r2, off);
                }
                if (tid == 0) g_rowconst[n] = fmaf(0.5f * ratio_p[0], r, -r2);
            }

            uint32_t* row32 = reinterpret_cast<uint32_t*>(g_A + (size_t)n * KP2);
            for (int l2 = tid; l2 < KP2 / 2; l2 += 256) {
                int l = 2 * l2;
                float v0 = 0.f, v1 = 0.f;
                if (l < KTRI) {
                    int2 ab0 = l2ab(l), ab1 = l2ab(l + 1);
                    v0 = (ab0.x == ab0.y) ? sM[ab0.x * 65 + ab0.x]
                                          : sM[ab0.x * 65 + ab0.y] + sM[ab0.y * 65 + ab0.x];
                    v1 = (ab1.x == ab1.y) ? sM[ab1.x * 65 + ab1.x]
                                          : sM[ab1.x * 65 + ab1.y] + sM[ab1.y * 65 + ab1.x];
                } else if (l < KP) {
                    v0 = -su[l - KTRI];
                    v1 = -su[l + 1 - KTRI];
                }
                __nv_bfloat162 h = __floats2bfloat162_rn(v0, v1);
                row32[l2] = *reinterpret_cast<uint32_t*>(&h);
            }
            __syncthreads();   // protect sM/su before next rep overwrites
        }
    }
}

// ---------------- GEMM (256 thr, 8 warps x 64x64, BK=64, frag double-buffer) ----------------
__global__ void __launch_bounds__(256, 1) gemm_kernel(
    const float* __restrict__ ratio_p, const float* __restrict__ Y,
    const int* __restrict__ tgt, float* __restrict__ yout,
    float* __restrict__ lossout)
{
    extern __shared__ char smem[];
    const uint32_t sbase = smem_u32(smem);
    const int tid  = threadIdx.x;
    const int wid  = tid >> 5;
    const int lane = tid & 31;
    const int gid  = lane >> 2;
    const int tig  = lane & 3;
    const int m0 = blockIdx.x * BM;
    const int c0 = blockIdx.y * BN;
    const int wm0 = (wid >> 2) * 64;     // 0, 64
    const int wn0 = (wid & 3) * 64;      // 0,64,128,192

    // ldmatrix lane-constant offsets
    const int l15 = lane & 15;
    const uint32_t A_lane_off = (uint32_t)(l15 * 32 + (((lane >> 4) ^ ((l15 >> 2) & 1)) << 4));
    const int swz3 = (l15 >> 1) & 3;
    const uint32_t B_col_base = (uint32_t)((wn0 + l15) * 64);
    const int bq_half = lane >> 4;

    // hoisted fill offsets: A 4 chunks/thread, B 8 chunks/thread
    uint32_t aoffS[4], aoffG[4], boffS[8], boffG[8];
    #pragma unroll
    for (int i = 0; i < 4; i++) {
        int ch = tid + i * 256;              // 0..1023
        int hh = ch >> 9, rem = ch & 511;
        int row = rem >> 2, q = rem & 3;
        aoffS[i] = (uint32_t)(hh * 8192 + (q >> 1) * 4096 + row * 32 +
                              (((q & 1) ^ ((row >> 2) & 1)) << 4));
        aoffG[i] = (uint32_t)((m0 + row) * (KP2 * 2) + hh * 64 + q * 16);
    }
    #pragma unroll
    for (int i = 0; i < 8; i++) {
        int ch = tid + i * 256;              // 0..2047
        int hh = ch >> 10, rem = ch & 1023;
        int col = rem >> 2, cq = rem & 3;
        boffS[i] = (uint32_t)(hh * 16384 + col * 64 + ((cq ^ ((col >> 1) & 3)) << 4));
        boffG[i] = (uint32_t)(hh * (CPAD * 64) + col * 64 + cq * 16);
    }
    const char* pA = reinterpret_cast<const char*>(g_A);                     // +128B/fill
    const char* pB = reinterpret_cast<const char*>(g_B) + (size_t)c0 * 64;   // +CPAD*128/fill

    float acc[4][8][4];
    #pragma unroll
    for (int i = 0; i < 4; i++)
        #pragma unroll
        for (int j = 0; j < 8; j++)
            #pragma unroll
            for (int r = 0; r < 4; r++) acc[i][j][r] = 0.f;

    auto fill = [&](int s) {
        uint32_t bA = sbase + s * STAGE_B;
        uint32_t bB = bA + A_TILE_B;
        #pragma unroll
        for (int i = 0; i < 4; i++) cpasync16(bA + aoffS[i], pA + aoffG[i]);
        #pragma unroll
        for (int i = 0; i < 8; i++) cpasync16(bB + boffS[i], pB + boffG[i]);
        asm volatile("cp.async.commit_group;\n" ::: "memory");
        pA += 128;
        pB += (size_t)CPAD * 128;
    };

    uint32_t f0a[4][4], f0b[8][2], f1a[4][4], f1b[8][2];

    // phase p in 0..3: A offset p*4096; B offset (p>>1)*16384 with q = (p&1)*2+bq_half
    auto ldA = [&](uint32_t bA, int p, uint32_t a[4][4]) {
        #pragma unroll
        for (int mt = 0; mt < 4; mt++)
            ldsm4(a[mt], bA + p * 4096 + (wm0 + mt * 16) * 32 + A_lane_off);
    };
    auto ldB = [&](uint32_t bB, int p, uint32_t b[8][2]) {
        #pragma unroll
        for (int ntp = 0; ntp < 4; ntp++) {
            uint32_t r[4];
            int q = (p & 1) * 2 + bq_half;
            ldsm4(r, bB + (p >> 1) * 16384 + B_col_base + ntp * 1024 + ((q ^ swz3) << 4));
            b[2 * ntp][0] = r[0]; b[2 * ntp][1] = r[2];
            b[2 * ntp + 1][0] = r[1]; b[2 * ntp + 1][1] = r[3];
        }
    };
    auto mma_all = [&](uint32_t a[4][4], uint32_t b[8][2]) {
        #pragma unroll
        for (int mt = 0; mt < 4; mt++)
            #pragma unroll
            for (int nt = 0; nt < 8; nt++)
                mma_bf16(acc[mt][nt], a[mt], b[nt]);
    };

    fill(0); fill(1); fill(2);
    asm volatile("cp.async.wait_group 2;\n" ::: "memory");
    __syncthreads();
    ldA(sbase, 0, f0a); ldB(sbase + A_TILE_B, 0, f0b);

    int s = 0;
    for (int kt = 0; kt < KT2; kt++) {
        const uint32_t bA = sbase + s * STAGE_B;
        const uint32_t bB = bA + A_TILE_B;
        ldA(bA, 1, f1a); ldB(bB, 1, f1b);
        mma_all(f0a, f0b);
        ldA(bA, 2, f0a); ldB(bB, 2, f0b);
        mma_all(f1a, f1b);
        ldA(bA, 3, f1a); ldB(bB, 3, f1b);
        mma_all(f0a, f0b);
        asm volatile("cp.async.wait_group 1;\n" ::: "memory");
        __syncthreads();
        // preload next tile's phase-0 fragments FIRST (critical path), then refill
        int s1 = (s + 1) & 3;
        if (kt + 1 < KT2) {
            uint32_t bA1 = sbase + s1 * STAGE_B;
            ldA(bA1, 0, f0a); ldB(bA1 + A_TILE_B, 0, f0b);
        }
        if (kt + 3 < KT2) {
            fill((s + 3) & 3);
        } else {
            asm volatile("cp.async.commit_group;\n" ::: "memory");
        }
        mma_all(f1a, f1b);
        s = s1;
    }
    __syncthreads();   // mainloop smem dead; reuse for reductions

    // ---- fused epilogue: per-row (max, sumexp) partial + target logit + Y out ----
    float* sR = reinterpret_cast<float*>(smem);         // [8][64]
    float* sS = reinterpret_cast<float*>(smem) + 512;   // [8][64]
    int*   sFlag = reinterpret_cast<int*>(smem) + 1024;
    const float hr = 0.5f * ratio_p[0];

    int   tcol[4][2];
    float rc[4][2];
    #pragma unroll
    for (int mt = 0; mt < 4; mt++)
        #pragma unroll
        for (int h = 0; h < 2; h++) {
            int rglob = m0 + wm0 + mt * 16 + gid + 8 * h;
            tcol[mt][h] = tgt[rglob];
            rc[mt][h] = g_rowconst[rglob];
        }

    float rmax[4][2];
    #pragma unroll
    for (int mt = 0; mt < 4; mt++) { rmax[mt][0] = -1e30f; rmax[mt][1] = -1e30f; }

    #pragma unroll
    for (int nt = 0; nt < 8; nt++) {
        int col = c0 + wn0 + nt * 8 + 2 * tig;
        bool ok = (col < CC);          // col even, CC even -> col+1 < CC too
        float w20 = g_w2[col], w21 = g_w2[col + 1];
        #pragma unroll
        for (int mt = 0; mt < 4; mt++) {
            #pragma unroll
            for (int h = 0; h < 2; h++) {
                int rglob = m0 + wm0 + mt * 16 + gid + 8 * h;
                float y0 = 0.f, y1 = 0.f;
                if (ok) {
                    float2 yv = *reinterpret_cast<const float2*>(Y + (size_t)rglob * CC + col);
                    y0 = yv.x; y1 = yv.y;
                    if (yout) {
                        // scalar stores: yout = out+1 is only 4B-aligned
                        yout[(size_t)rglob * CC + col]     = y0;
                        yout[(size_t)rglob * CC + col + 1] = y1;
                    }
                }
                float v0 = ok ? fmaf(hr, acc[mt][nt][2 * h + 0], rc[mt][h] + w20 + y0) : -1e30f;
                float v1 = ok ? fmaf(hr, acc[mt][nt][2 * h + 1], rc[mt][h] + w21 + y1) : -1e30f;
                if (col == tcol[mt][h])     g_lk[rglob] = v0;
                if (col + 1 == tcol[mt][h]) g_lk[rglob] = v1;
                acc[mt][nt][2 * h + 0] = v0;
                acc[mt][nt][2 * h + 1] = v1;
                rmax[mt][h] = fmaxf(rmax[mt][h], fmaxf(v0, v1));
            }
        }
    }
    #pragma unroll
    for (int mt = 0; mt < 4; mt++)
        #pragma unroll
        for (int h = 0; h < 2; h++) {
            rmax[mt][h] = fmaxf(rmax[mt][h], __shfl_xor_sync(0xffffffffu, rmax[mt][h], 1));
            rmax[mt][h] = fmaxf(rmax[mt][h], __shfl_xor_sync(0xffffffffu, rmax[mt][h], 2));
        }
    if (tig == 0) {
        #pragma unroll
        for (int mt = 0; mt < 4; mt++)
            #pragma unroll
            for (int h = 0; h < 2; h++)
                sR[wid * 64 + mt * 16 + gid + 8 * h] = rmax[mt][h];
    }
    __syncthreads();
    const int wg4 = (wid >> 2) * 4;      // 4 warps sharing my rows
    float Mf[4][2];
    #pragma unroll
    for (int mt = 0; mt < 4; mt++)
        #pragma unroll
        for (int h = 0; h < 2; h++) {
            int idx = mt * 16 + gid + 8 * h;
            float mv = sR[wg4 * 64 + idx];
            mv = fmaxf(mv, sR[(wg4 + 1) * 64 + idx]);
            mv = fmaxf(mv, sR[(wg4 + 2) * 64 + idx]);
            mv = fmaxf(mv, sR[(wg4 + 3) * 64 + idx]);
            Mf[mt][h] = mv;
        }
    float rsum[4][2];
    #pragma unroll
    for (int mt = 0; mt < 4; mt++) { rsum[mt][0] = 0.f; rsum[mt][1] = 0.f; }
    #pragma unroll
    for (int nt = 0; nt < 8; nt++)
        #pragma unroll
        for (int mt = 0; mt < 4; mt++)
            #pragma unroll
            for (int h = 0; h < 2; h++) {
                rsum[mt][h] += fexp_fma(fmaxf(acc[mt][nt][2 * h + 0] - Mf[mt][h], -80.f));
                rsum[mt][h] += fexp_fma(fmaxf(acc[mt][nt][2 * h + 1] - Mf[mt][h], -80.f));
            }
    #pragma unroll
    for (int mt = 0; mt < 4; mt++)
        #pragma unroll
        for (int h = 0; h < 2; h++) {
            rsum[mt][h] += __shfl_xor_sync(0xffffffffu, rsum[mt][h], 1);
            rsum[mt][h] += __shfl_xor_sync(0xffffffffu, rsum[mt][h], 2);
        }
    __syncthreads();
    if (tig == 0) {
        #pragma unroll
        for (int mt = 0; mt < 4; mt++)
            #pragma unroll
            for (int h = 0; h < 2; h++)
                sS[wid * 64 + mt * 16 + gid + 8 * h] = rsum[mt][h];
    }
    __syncthreads();
    if (tig == 0 && (wid & 3) == 0) {
        const int ct = blockIdx.y;
        #pragma unroll
        for (int mt = 0; mt < 4; mt++)
            #pragma unroll
            for (int h = 0; h < 2; h++) {
                int idx = mt * 16 + gid + 8 * h;
                int rglob = m0 + wm0 + idx;
                float ssum = sS[wg4 * 64 + idx] + sS[(wg4 + 1) * 64 + idx]
                           + sS[(wg4 + 2) * 64 + idx] + sS[(wg4 + 3) * 64 + idx];
                g_pmax[ct * NB + rglob] = Mf[mt][h];
                g_psum[ct * NB + rglob] = ssum;
            }
    }

    // ---- fused cross-CTA combine ----
    __threadfence();
    __syncthreads();
    if (tid == 0) sFlag[0] = atomicAdd(&g_cnt_row[blockIdx.x], 1);
    __syncthreads();
    if (sFlag[0] != NCTA_C - 1) return;

    __threadfence();
    if (tid < BM) {
        int n = m0 + tid;
        float M = g_pmax[n];
        #pragma unroll
        for (int i = 1; i < NCTA_C; i++) M = fmaxf(M, g_pmax[i * NB + n]);
        float S = 0.f;
        #pragma unroll
        for (int i = 0; i < NCTA_C; i++)
            S += g_psum[i * NB + n] * fexp_fma(fmaxf(g_pmax[i * NB + n] - M, -80.f));
        g_nll[n] = (M + logf(S)) - g_lk[n];
    }
    __threadfence();
    __syncthreads();
    if (tid == 0) sFlag[0] = atomicAdd(&g_cnt_all, 1);
    __syncthreads();
    if (sFlag[0] != NB / BM - 1) return;

    __threadfence();
    float accl = 0.f;
    const float4* p = reinterpret_cast<const float4*>(g_nll);
    for (int i = tid; i < NB / 4; i += 256) {
        float4 v = p[i];
        accl += (v.x + v.y) + (v.z + v.w);
    }
    sR[tid] = accl;
    __syncthreads();
    #pragma unroll
    for (int off = 128; off > 0; off >>= 1) {
        if (tid < off) sR[tid] += sR[tid + off];
        __syncthreads();
    }
    if (tid == 0) lossout[0] = sR[0] * (1.0f / NB);
}

// ---------------- host ----------------
extern "C" void kernel_launch(void* const* d_in, const int* in_sizes, int n_in,
                              void* d_out, int out_size)
{
    const float* W     = (const float*)d_in[0];
    const float* Y     = (const float*)d_in[1];
    const int*   tgt   = (const int*)  d_in[3];
    const float* ratio = (const float*)d_in[4];
    const float* CV    = (const float*)d_in[5];
    float* out = (float*)d_out;

    cudaFuncSetAttribute(gemm_kernel, cudaFuncAttributeMaxDynamicSharedMemorySize, SMEM_TOTAL);

    const bool std_layout = (out_size >= 1 + NB * CC);
    float* yout = std_layout ? (out + 1) : nullptr;
    float* lossout;
    if (std_layout) lossout = out;
    else cudaGetSymbolAddress((void**)&lossout, g_dummy);

    prep_kernel<<<64 + NB / 2, 256>>>(W, tgt, ratio, CV);
    gemm_kernel<<<dim3(NB / BM, CPAD / BN), 256, SMEM_TOTAL>>>(ratio, Y, tgt, yout, lossout);

    if (!std_layout && out_size == NB * CC) {
        cudaMemcpyAsync(out, Y, (size_t)NB * CC * sizeof(float),
                        cudaMemcpyDeviceToDevice, 0);
    }
}